// round 13
// baseline (speedup 1.0000x reference)
#include <cuda_runtime.h>
#include <cuda_bf16.h>
#include <math.h>

#define LDOC 200
#define HDIM 384
#define EDIM 768
#define NBLK 144                         // 4 cells x 2 row-halves x 18 j-slices
#define NTHR 704                         // 22 warps, 1 j per warp
#define SROW 289                         // float4 per staged row (288 data + 1 pad)
#define SMEM_BYTES (32 * SROW * 16)      // 147,968 bytes
#define NQ 288                           // K/4 = (768+384)/4 float4-chunks per gate row

// Persistent device state.
__device__ __align__(16) float g_h[2][4][64][HDIM];   // [parity][cell][row][j]
__device__ unsigned long long g_bar;
// Packed weights: [cell][j][q][gate] float4. One contiguous 18.4KB stream per (cell,j).
__device__ __align__(16) float4 g_wpack[4][384][NQ][4];   // 28.3 MB

__device__ __forceinline__ void grid_barrier() {
    __threadfence();
    __syncthreads();
    if (threadIdx.x == 0) {
        unsigned long long old = atomicAdd(&g_bar, 1ULL);
        unsigned long long tgt = (old / (unsigned long long)NBLK + 1ULL) * (unsigned long long)NBLK;
        while (*((volatile unsigned long long*)&g_bar) < tgt) {
            __nanosleep(32);
        }
        __threadfence();
    }
    __syncthreads();
}

__device__ __forceinline__ void fma4(float& a, const float4 x, const float4 w) {
    a = fmaf(x.x, w.x, a);
    a = fmaf(x.y, w.y, a);
    a = fmaf(x.z, w.z, a);
    a = fmaf(x.w, w.w, a);
}

__device__ __forceinline__ float sigm(float v) { return 1.0f / (1.0f + expf(-v)); }

// One-shot (per launch) repack: W_ih[cell][gate*384+j][0:768] ++ W_hh[cell][gate*384+j][0:384]
// -> g_wpack[cell][j][q][gate], gates interleaved per q for a single sequential stream.
__global__ void pack_weights(const float* __restrict__ W_ih, const float* __restrict__ W_hh) {
    const int total = 4 * 384 * NQ * 4;     // 1,769,472 float4
    for (int idx = blockIdx.x * blockDim.x + threadIdx.x; idx < total;
         idx += gridDim.x * blockDim.x) {
        const int g    = idx & 3;
        const int q    = (idx >> 2) % NQ;
        const int j    = ((idx >> 2) / NQ) % 384;
        const int cell = (idx >> 2) / (NQ * 384);
        const float* src;
        if (q < 192) {
            src = W_ih + ((size_t)cell * 1536 + g * 384 + j) * EDIM + q * 4;
        } else {
            src = W_hh + ((size_t)cell * 1536 + g * 384 + j) * HDIM + (q - 192) * 4;
        }
        g_wpack[cell][j][q][g] = *(const float4*)src;
    }
}

__global__ __launch_bounds__(NTHR, 1)
void lstm_persistent(const int*   __restrict__ contexts,   // [64][200]
                     const int*   __restrict__ positions,  // [64]
                     const float* __restrict__ W_emb,      // [50000][768]
                     const float* __restrict__ b_lstm,     // [4][1536]
                     const float* __restrict__ W_cls,      // [2][768]
                     const float* __restrict__ b_cls,      // [2]
                     float*       __restrict__ out)        // logits[128] | probs[128] | target[64*768]
{
    extern __shared__ float4 sm[];
    const int tid  = threadIdx.x;
    const int bid  = blockIdx.x;
    const int cell = bid / 36;              // 0..3  (0,1 = layer0; 2,3 = layer1)
    const int rem  = bid - cell * 36;
    const int rh   = rem / 18;              // row half: rows [rh*32, rh*32+32)
    const int js   = rem - rh * 18;         // j-slice 0..17
    const int j0   = (js * 384) / 18;
    const int j1   = ((js + 1) * 384) / 18; // 21 or 22 j's per slice
    const int w    = tid >> 5;              // warp 0..21
    const int lane = tid & 31;
    const int row  = rh * 32 + lane;
    const int jA   = j0 + w;
    const bool act_j = (jA < j1);           // warp-uniform
    const bool isL1  = (cell >= 2);

    // ---- zero h state (both parities) ----
    {
        float4 z = make_float4(0.f, 0.f, 0.f, 0.f);
        float4* hp = (float4*)g_h;
        const int n4 = 2 * 4 * 64 * HDIM / 4;   // 49152
        for (int i = bid * NTHR + tid; i < n4; i += NBLK * NTHR) hp[i] = z;
    }
    grid_barrier();

    float cA = 0.f;                         // cell state in registers, forever
    const int pos = __ldg(&positions[row]);
    float* tgt = out + 256;

    const float4* wp = &g_wpack[cell][jA][0][0];   // contiguous 1152 float4
    const float* bb = b_lstm + cell * 1536;
    const float biI = __ldg(bb + jA),        biF = __ldg(bb + 384 + jA);
    const float biG = __ldg(bb + 768 + jA),  biO = __ldg(bb + 1152 + jA);

    // Pipelined phases: layer0 computes step t=p while layer1 computes step t=p-1.
    for (int p = 0; p <= LDOC; p++) {
        const int par_w = p & 1;
        const int par_r = par_w ^ 1;
        const int t = isL1 ? (p - 1) : p;
        const bool active = isL1 ? (p >= 1) : (p < LDOC);   // block-uniform

        if (active) {
            // ---- stage input [32 rows][288 float4] into SMEM ----
            for (int idx = tid; idx < 32 * 288; idx += NTHR) {
                const int r = idx / 288;
                const int q = idx - r * 288;
                const int srow = rh * 32 + r;
                float4 v;
                if (q < 192) {
                    if (!isL1) {
                        const int tok = __ldg(&contexts[srow * LDOC + t]);
                        v = __ldg((const float4*)(W_emb + (size_t)tok * EDIM) + q);
                    } else {
                        const int half = (q >= 96) ? 1 : 0;
                        v = __ldcg((const float4*)(&g_h[par_r][half][srow][0]) + (q - 96 * half));
                    }
                } else {
                    v = __ldcg((const float4*)(&g_h[par_r][cell][srow][0]) + (q - 192));
                }
                sm[r * SROW + q] = v;
            }
            __syncthreads();

            if (act_j) {
                float ai = biI, af = biF, ag = biG, ao = biO;
                const float4* xr = sm + lane * SROW;

                // ---- software-pipelined weight stream: chunks of 4 q, double-buffered ----
                float4 wa[16], wb[16];
                #pragma unroll
                for (int k = 0; k < 16; k++) wa[k] = __ldg(wp + k);

                #pragma unroll 1
                for (int ch = 0; ch < 72; ch += 2) {
                    const float4* p1 = wp + (ch + 1) * 16;
                    #pragma unroll
                    for (int k = 0; k < 16; k++) wb[k] = __ldg(p1 + k);
                    #pragma unroll
                    for (int u = 0; u < 4; u++) {
                        const float4 x = xr[ch * 4 + u];
                        fma4(ai, x, wa[u * 4 + 0]);
                        fma4(af, x, wa[u * 4 + 1]);
                        fma4(ag, x, wa[u * 4 + 2]);
                        fma4(ao, x, wa[u * 4 + 3]);
                    }
                    if (ch + 2 < 72) {
                        const float4* p2 = wp + (ch + 2) * 16;
                        #pragma unroll
                        for (int k = 0; k < 16; k++) wa[k] = __ldg(p2 + k);
                    }
                    #pragma unroll
                    for (int u = 0; u < 4; u++) {
                        const float4 x = xr[(ch + 1) * 4 + u];
                        fma4(ai, x, wb[u * 4 + 0]);
                        fma4(af, x, wb[u * 4 + 1]);
                        fma4(ag, x, wb[u * 4 + 2]);
                        fma4(ao, x, wb[u * 4 + 3]);
                    }
                }

                // ---- activations + state update ----
                cA = sigm(af) * cA + sigm(ai) * tanhf(ag);
                const float hA = sigm(ao) * tanhf(cA);

                __stcg(&g_h[par_w][cell][row][jA], hA);

                if (isL1 && t == pos) {
                    __stcg(&tgt[row * 768 + (cell - 2) * 384 + jA], hA);
                }
            }
        }
        grid_barrier();
    }

    // ---- classifier head ----
    if (bid == 0 && tid < 128) {
        const int b = tid >> 1;
        const int c = tid & 1;
        const float4* tv = (const float4*)(tgt + b * 768);
        const float4* wv = (const float4*)(W_cls + c * 768);
        float acc = __ldg(&b_cls[c]);
        #pragma unroll 4
        for (int q = 0; q < 192; q++) {
            const float4 x = __ldcg(tv + q);
            const float4 ww = __ldg(wv + q);
            acc = fmaf(x.x, ww.x, acc);
            acc = fmaf(x.y, ww.y, acc);
            acc = fmaf(x.z, ww.z, acc);
            acc = fmaf(x.w, ww.w, acc);
        }
        out[tid] = acc;                              // logits [64][2]
        out[128 + tid] = 1.0f / (1.0f + expf(-acc)); // probs  [64][2]
    }
}

extern "C" void kernel_launch(void* const* d_in, const int* in_sizes, int n_in,
                              void* d_out, int out_size) {
    (void)in_sizes; (void)n_in; (void)out_size;
    cudaFuncSetAttribute(lstm_persistent, cudaFuncAttributeMaxDynamicSharedMemorySize, SMEM_BYTES);
    pack_weights<<<512, 256>>>((const float*)d_in[3], (const float*)d_in[4]);
    lstm_persistent<<<NBLK, NTHR, SMEM_BYTES>>>(
        (const int*)d_in[0],     // contexts
        (const int*)d_in[1],     // positions
        (const float*)d_in[2],   // W_emb
        (const float*)d_in[5],   // b_lstm
        (const float*)d_in[6],   // W_cls
        (const float*)d_in[7],   // b_cls
        (float*)d_out);
}

// round 14
// speedup vs baseline: 5.3619x; 5.3619x over previous
#include <cuda_runtime.h>
#include <cuda_bf16.h>
#include <math.h>
#include <stdint.h>

#define LDOC 200
#define NBLK 128
#define NTHR 256
#define KC   128                      // k elements per chunk
#define NCH  9                        // 1152 / 128
#define AROW 272                      // smem row stride bytes (256 data + 16 pad)
#define A_SZ (64 * AROW)              // 17408  (x tile, one term)
#define B_SZ (48 * AROW)              // 13056  (w tile, one term)
#define BUF_SZ (2 * A_SZ + 2 * B_SZ)  // 60928
#define SMEM_BYTES (2 * BUF_SZ)       // 121856

// Persistent device state
__device__ __align__(16) float g_h[2][4][64][384];    // [parity][cell][row][j]
__device__ unsigned long long g_bar;                  // monotonic -> graph-replay safe
// Packed split weights: [cell][slice][chunk][hi/lo][n=48][k=128] bf16  (28.3 MB)
__device__ __align__(16) __nv_bfloat16 g_wpk[4][32][NCH][2][48][KC];

__device__ __forceinline__ void grid_barrier() {
    __threadfence();
    __syncthreads();
    if (threadIdx.x == 0) {
        unsigned long long old = atomicAdd(&g_bar, 1ULL);
        unsigned long long tgt = (old / (unsigned long long)NBLK + 1ULL) * (unsigned long long)NBLK;
        while (*((volatile unsigned long long*)&g_bar) < tgt) { __nanosleep(32); }
        __threadfence();
    }
    __syncthreads();
}

__device__ __forceinline__ float sigm(float v) { return 1.0f / (1.0f + expf(-v)); }

__device__ __forceinline__ void ldsm_x4(uint32_t& r0, uint32_t& r1, uint32_t& r2, uint32_t& r3, uint32_t addr) {
    asm volatile("ldmatrix.sync.aligned.m8n8.x4.shared.b16 {%0,%1,%2,%3},[%4];"
                 : "=r"(r0), "=r"(r1), "=r"(r2), "=r"(r3) : "r"(addr));
}
__device__ __forceinline__ void ldsm_x2(uint32_t& r0, uint32_t& r1, uint32_t addr) {
    asm volatile("ldmatrix.sync.aligned.m8n8.x2.shared.b16 {%0,%1},[%2];"
                 : "=r"(r0), "=r"(r1) : "r"(addr));
}
__device__ __forceinline__ void mma_bf16(float& d0, float& d1, float& d2, float& d3,
                                         uint32_t a0, uint32_t a1, uint32_t a2, uint32_t a3,
                                         uint32_t b0, uint32_t b1) {
    asm volatile("mma.sync.aligned.m16n8k16.row.col.f32.bf16.bf16.f32 "
                 "{%0,%1,%2,%3},{%4,%5,%6,%7},{%8,%9},{%0,%1,%2,%3};"
                 : "+f"(d0), "+f"(d1), "+f"(d2), "+f"(d3)
                 : "r"(a0), "r"(a1), "r"(a2), "r"(a3), "r"(b0), "r"(b1));
}
__device__ __forceinline__ void cp16(uint32_t dst, const void* src) {
    asm volatile("cp.async.ca.shared.global [%0],[%1],16;" :: "r"(dst), "l"(src));
}
__device__ __forceinline__ uint32_t pack2(__nv_bfloat16 a, __nv_bfloat16 b) {
    return (uint32_t)__bfloat16_as_ushort(a) | ((uint32_t)__bfloat16_as_ushort(b) << 16);
}

// One-shot per launch: split fp32 weights into bf16 hi/lo, packed per block slice.
// packed col n within slice ns: j = ns*12 + (n>>2), gate = n&3, G = gate*384 + j.
__global__ void pack_weights(const float* __restrict__ W_ih, const float* __restrict__ W_hh) {
    const long total = 4L * 32 * NCH * 48 * KC;   // 7,077,888
    for (long idx = (long)blockIdx.x * blockDim.x + threadIdx.x; idx < total;
         idx += (long)gridDim.x * blockDim.x) {
        int k  = (int)(idx % KC);
        long r = idx / KC;
        int n  = (int)(r % 48); r /= 48;
        int ch = (int)(r % NCH); r /= NCH;
        int ns = (int)(r % 32);
        int cell = (int)(r / 32);
        int j = ns * 12 + (n >> 2);
        int G = (n & 3) * 384 + j;
        int kg = ch * KC + k;
        float w = (kg < 768) ? W_ih[((long)cell * 1536 + G) * 768 + kg]
                             : W_hh[((long)cell * 1536 + G) * 384 + (kg - 768)];
        __nv_bfloat16 hi = __float2bfloat16(w);
        __nv_bfloat16 lo = __float2bfloat16(w - __bfloat162float(hi));
        g_wpk[cell][ns][ch][0][n][k] = hi;
        g_wpk[cell][ns][ch][1][n][k] = lo;
    }
}

__global__ __launch_bounds__(NTHR, 1)
void lstm_mma(const int*   __restrict__ contexts,   // [64][200]
              const int*   __restrict__ positions,  // [64]
              const float* __restrict__ W_emb,      // [50000][768]
              const float* __restrict__ b_lstm,     // [4][1536]
              const float* __restrict__ W_cls,      // [2][768]
              const float* __restrict__ b_cls,      // [2]
              float*       __restrict__ out)        // logits[128] | probs[128] | target[64*768]
{
    extern __shared__ __align__(16) char sm[];
    const uint32_t sb32 = (uint32_t)__cvta_generic_to_shared(sm);

    const int tid  = threadIdx.x;
    const int bid  = blockIdx.x;
    const int cell = bid >> 5;            // 0..3
    const int ns   = bid & 31;            // j-slice (12 j's)
    const bool isL1 = (cell >= 2);
    const int w    = tid >> 5;            // warp 0..7
    const int lane = tid & 31;
    const int mt   = w & 3;               // m-tile (rows 16mt..16mt+15)
    const int ng   = w >> 2;              // n-group (cols 24ng..24ng+23)

    // ---- per-lane ldmatrix offsets (byte offsets inside a term region) ----
    const uint32_t a_off = (uint32_t)((mt * 16 + (lane & 7) + ((lane >> 3) & 1) * 8) * AROW
                                      + (lane >> 4) * 16);
    const int bm = lane >> 3;
    const uint32_t b01_off = (uint32_t)((ng * 24 + (bm >> 1) * 8 + (lane & 7)) * AROW + (bm & 1) * 16);
    const int ln2 = lane & 15;
    const uint32_t b2_off  = (uint32_t)((ng * 24 + 16 + (ln2 & 7)) * AROW + (ln2 >> 3) * 16);

    // ---- zero h state (both parities) ----
    {
        float4 z = make_float4(0.f, 0.f, 0.f, 0.f);
        float4* hp = (float4*)g_h;
        const int n4 = 2 * 4 * 64 * 384 / 4;
        for (int i = bid * NTHR + tid; i < n4; i += NBLK * NTHR) hp[i] = z;
    }
    grid_barrier();

    // ---- persistent per-thread state ----
    const int r0 = mt * 16 + (lane >> 2);             // my row, and r0+8
    const int q  = lane & 3;
    float cst[6] = {0, 0, 0, 0, 0, 0};                // [nt][row0/row1], even-q lanes only
    const int pr0 = __ldg(&positions[r0]);
    const int pr1 = __ldg(&positions[r0 + 8]);
    float* tgt = out + 256;

    // biases for my 2 columns per n-tile: col = nb + 2q (+1)
    float bc0[3], bc1[3];
    #pragma unroll
    for (int nt = 0; nt < 3; nt++) {
        const int nb = ng * 24 + nt * 8;
        const int c0 = nb + 2 * q;
        const int G0 = (c0 & 3) * 384 + ns * 12 + (c0 >> 2);
        const int c1 = c0 + 1;
        const int G1 = (c1 & 3) * 384 + ns * 12 + (c1 >> 2);
        bc0[nt] = __ldg(&b_lstm[cell * 1536 + G0]);
        bc1[nt] = __ldg(&b_lstm[cell * 1536 + G1]);
    }

    const char* wsrc_base = (const char*)&g_wpk[cell][ns][0][0][0][0];

    for (int p = 0; p <= LDOC; p++) {
        const int par_w = p & 1;
        const int par_r = par_w ^ 1;
        const int t = isL1 ? (p - 1) : p;
        const bool active = isL1 ? (p >= 1) : (p < LDOC);

        if (active) {
            float acc[12];
            #pragma unroll
            for (int nt = 0; nt < 3; nt++) {
                acc[nt * 4 + 0] = bc0[nt]; acc[nt * 4 + 1] = bc1[nt];
                acc[nt * 4 + 2] = bc0[nt]; acc[nt * 4 + 3] = bc1[nt];
            }

            // ---------- staging helpers (inlined) ----------
            // W: cp.async 1536 x 16B per chunk;  x: 8 float4 per thread, split to hi/lo
            auto stage_W = [&](int ch, int b) {
                const char* src = wsrc_base + (long)ch * (2 * 48 * KC * 2);
                const uint32_t base = sb32 + b * BUF_SZ + 2 * A_SZ;
                for (int g16 = tid; g16 < 1536; g16 += NTHR) {
                    const int tm = g16 >> 9 >> 1;            // /1024? no: 768 per term
                    const int tm2 = g16 / 768;
                    const int rem = g16 - tm2 * 768;
                    const int n = rem >> 4, c = rem & 15;
                    cp16(base + tm2 * B_SZ + n * AROW + c * 16, src + (long)g16 * 16);
                    (void)tm;
                }
                asm volatile("cp.async.commit_group;");
            };
            auto load_x = [&](int ch, float4* xa) {
                #pragma unroll
                for (int ii = 0; ii < 8; ii++) {
                    const int f = tid + ii * NTHR;
                    const int row = f >> 5, kc4 = f & 31;
                    const int kg = ch * KC + kc4 * 4;
                    const float* src;
                    bool use_ldg = false;
                    if (!isL1) {
                        if (kg < 768) {
                            const int tok = __ldg(&contexts[row * LDOC + t]);
                            src = W_emb + (size_t)tok * 768 + kg;
                            use_ldg = true;
                        } else src = &g_h[par_r][cell][row][kg - 768];
                    } else {
                        if (kg < 384)      src = &g_h[par_r][0][row][kg];
                        else if (kg < 768) src = &g_h[par_r][1][row][kg - 384];
                        else               src = &g_h[par_r][cell][row][kg - 768];
                    }
                    xa[ii] = use_ldg ? __ldg((const float4*)src) : __ldcg((const float4*)src);
                }
            };
            auto store_x = [&](const float4* xa, int b) {
                char* ah = sm + b * BUF_SZ;
                char* al = ah + A_SZ;
                #pragma unroll
                for (int ii = 0; ii < 8; ii++) {
                    const int f = tid + ii * NTHR;
                    const int row = f >> 5, kc4 = f & 31;
                    const float4 x = xa[ii];
                    __nv_bfloat16 h0 = __float2bfloat16(x.x), h1 = __float2bfloat16(x.y);
                    __nv_bfloat16 h2 = __float2bfloat16(x.z), h3 = __float2bfloat16(x.w);
                    __nv_bfloat16 l0 = __float2bfloat16(x.x - __bfloat162float(h0));
                    __nv_bfloat16 l1 = __float2bfloat16(x.y - __bfloat162float(h1));
                    __nv_bfloat16 l2 = __float2bfloat16(x.z - __bfloat162float(h2));
                    __nv_bfloat16 l3 = __float2bfloat16(x.w - __bfloat162float(h3));
                    *(uint2*)(ah + row * AROW + kc4 * 8) = make_uint2(pack2(h0, h1), pack2(h2, h3));
                    *(uint2*)(al + row * AROW + kc4 * 8) = make_uint2(pack2(l0, l1), pack2(l2, l3));
                }
            };
            auto mma_chunk = [&](int b) {
                const uint32_t ah_b = sb32 + b * BUF_SZ;
                const uint32_t al_b = ah_b + A_SZ;
                const uint32_t bh_b = ah_b + 2 * A_SZ;
                const uint32_t bl_b = bh_b + B_SZ;
                #pragma unroll
                for (int s = 0; s < 8; s++) {
                    const uint32_t so = (uint32_t)s * 32;
                    uint32_t ah[4], al[4], bh[6], bl[6];
                    ldsm_x4(ah[0], ah[1], ah[2], ah[3], ah_b + a_off + so);
                    ldsm_x4(al[0], al[1], al[2], al[3], al_b + a_off + so);
                    ldsm_x4(bh[0], bh[1], bh[2], bh[3], bh_b + b01_off + so);
                    ldsm_x2(bh[4], bh[5], bh_b + b2_off + so);
                    ldsm_x4(bl[0], bl[1], bl[2], bl[3], bl_b + b01_off + so);
                    ldsm_x2(bl[4], bl[5], bl_b + b2_off + so);
                    #pragma unroll
                    for (int nt = 0; nt < 3; nt++) {
                        float* c = acc + nt * 4;
                        mma_bf16(c[0], c[1], c[2], c[3], ah[0], ah[1], ah[2], ah[3], bh[nt * 2], bh[nt * 2 + 1]);
                        mma_bf16(c[0], c[1], c[2], c[3], ah[0], ah[1], ah[2], ah[3], bl[nt * 2], bl[nt * 2 + 1]);
                        mma_bf16(c[0], c[1], c[2], c[3], al[0], al[1], al[2], al[3], bh[nt * 2], bh[nt * 2 + 1]);
                    }
                }
            };
            // ---------- pipelined chunk loop ----------
            {
                float4 xa[8];
                stage_W(0, 0);
                load_x(0, xa);
                store_x(xa, 0);
                asm volatile("cp.async.wait_group 0;");
                __syncthreads();
                for (int i = 0; i < NCH; i++) {
                    const int b = i & 1;
                    if (i + 1 < NCH) { stage_W(i + 1, b ^ 1); load_x(i + 1, xa); }
                    mma_chunk(b);
                    if (i + 1 < NCH) {
                        store_x(xa, b ^ 1);
                        asm volatile("cp.async.wait_group 0;");
                    }
                    __syncthreads();
                }
            }

            // ---------- epilogue: assemble i,f,g,o per j via shfl, update c, store h ----------
            #pragma unroll
            for (int nt = 0; nt < 3; nt++) {
                float* a = acc + nt * 4;
                const float p0 = __shfl_xor_sync(0xFFFFFFFFu, a[0], 1);
                const float p1 = __shfl_xor_sync(0xFFFFFFFFu, a[1], 1);
                const float p2 = __shfl_xor_sync(0xFFFFFFFFu, a[2], 1);
                const float p3 = __shfl_xor_sync(0xFFFFFFFFu, a[3], 1);
                if ((lane & 1) == 0) {
                    // mine: i(r0), f(r0), i(r0+8), f(r0+8); partner: g(r0), o(r0), g(r0+8), o(r0+8)
                    const int jg = ns * 12 + (ng * 6 + nt * 2) + (q >> 1);
                    float cn0 = sigm(a[1]) * cst[nt * 2 + 0] + sigm(a[0]) * tanhf(p0);
                    float h0v = sigm(p1) * tanhf(cn0);
                    float cn1 = sigm(a[3]) * cst[nt * 2 + 1] + sigm(a[2]) * tanhf(p2);
                    float h1v = sigm(p3) * tanhf(cn1);
                    cst[nt * 2 + 0] = cn0;
                    cst[nt * 2 + 1] = cn1;
                    __stcg(&g_h[par_w][cell][r0][jg], h0v);
                    __stcg(&g_h[par_w][cell][r0 + 8][jg], h1v);
                    if (isL1) {
                        if (t == pr0) __stcg(&tgt[r0 * 768 + (cell - 2) * 384 + jg], h0v);
                        if (t == pr1) __stcg(&tgt[(r0 + 8) * 768 + (cell - 2) * 384 + jg], h1v);
                    }
                }
            }
        }
        grid_barrier();
    }

    // ---- classifier head ----
    if (bid == 0 && tid < 128) {
        const int b = tid >> 1;
        const int c = tid & 1;
        const float4* tv = (const float4*)(tgt + b * 768);
        const float4* wv = (const float4*)(W_cls + c * 768);
        float acc = __ldg(&b_cls[c]);
        #pragma unroll 4
        for (int qq = 0; qq < 192; qq++) {
            const float4 x = __ldcg(tv + qq);
            const float4 ww = __ldg(wv + qq);
            acc = fmaf(x.x, ww.x, acc);
            acc = fmaf(x.y, ww.y, acc);
            acc = fmaf(x.z, ww.z, acc);
            acc = fmaf(x.w, ww.w, acc);
        }
        out[tid] = acc;                              // logits [64][2]
        out[128 + tid] = 1.0f / (1.0f + expf(-acc)); // probs  [64][2]
    }
}

extern "C" void kernel_launch(void* const* d_in, const int* in_sizes, int n_in,
                              void* d_out, int out_size) {
    (void)in_sizes; (void)n_in; (void)out_size;
    cudaFuncSetAttribute(lstm_mma, cudaFuncAttributeMaxDynamicSharedMemorySize, SMEM_BYTES);
    pack_weights<<<512, 256>>>((const float*)d_in[3], (const float*)d_in[4]);
    lstm_mma<<<NBLK, NTHR, SMEM_BYTES>>>(
        (const int*)d_in[0],     // contexts
        (const int*)d_in[1],     // positions
        (const float*)d_in[2],   // W_emb
        (const float*)d_in[5],   // b_lstm
        (const float*)d_in[6],   // W_cls
        (const float*)d_in[7],   // b_cls
        (float*)d_out);
}

// round 15
// speedup vs baseline: 5.8555x; 1.0921x over previous
#include <cuda_runtime.h>
#include <cuda_bf16.h>
#include <math.h>
#include <stdint.h>

#define LDOC 200
#define NBLK 128
#define NTHR 512                      // 16 warps: 4 m-tiles x 2 n-groups x 2 k-groups
#define KC   128                      // k elements per chunk
#define NCH  9                        // 1152 / 128
#define AROW 272                      // smem row stride bytes (256 data + 16 pad)
#define A_SZ (64 * AROW)              // 17408  (x tile, one term)
#define B_SZ (48 * AROW)              // 13056  (w tile, one term)
#define BUF_SZ (2 * A_SZ + 2 * B_SZ)  // 60928
#define SMEM_BYTES (2 * BUF_SZ)       // 121856

// Persistent device state
__device__ __align__(16) float g_h[2][4][64][384];    // [parity][cell][row][j]
__device__ unsigned long long g_bar;                  // monotonic -> graph-replay safe
// Packed split weights: [cell][slice][chunk][hi/lo][n=48][k=128] bf16  (28.3 MB)
__device__ __align__(16) __nv_bfloat16 g_wpk[4][32][NCH][2][48][KC];

__device__ __forceinline__ void grid_barrier() {
    __threadfence();
    __syncthreads();
    if (threadIdx.x == 0) {
        unsigned long long old = atomicAdd(&g_bar, 1ULL);
        unsigned long long tgt = (old / (unsigned long long)NBLK + 1ULL) * (unsigned long long)NBLK;
        while (*((volatile unsigned long long*)&g_bar) < tgt) { __nanosleep(32); }
        __threadfence();
    }
    __syncthreads();
}

__device__ __forceinline__ float sigm(float v) { return 1.0f / (1.0f + expf(-v)); }

__device__ __forceinline__ void ldsm_x4(uint32_t& r0, uint32_t& r1, uint32_t& r2, uint32_t& r3, uint32_t addr) {
    asm volatile("ldmatrix.sync.aligned.m8n8.x4.shared.b16 {%0,%1,%2,%3},[%4];"
                 : "=r"(r0), "=r"(r1), "=r"(r2), "=r"(r3) : "r"(addr));
}
__device__ __forceinline__ void ldsm_x2(uint32_t& r0, uint32_t& r1, uint32_t addr) {
    asm volatile("ldmatrix.sync.aligned.m8n8.x2.shared.b16 {%0,%1},[%2];"
                 : "=r"(r0), "=r"(r1) : "r"(addr));
}
__device__ __forceinline__ void mma_bf16(float& d0, float& d1, float& d2, float& d3,
                                         uint32_t a0, uint32_t a1, uint32_t a2, uint32_t a3,
                                         uint32_t b0, uint32_t b1) {
    asm volatile("mma.sync.aligned.m16n8k16.row.col.f32.bf16.bf16.f32 "
                 "{%0,%1,%2,%3},{%4,%5,%6,%7},{%8,%9},{%0,%1,%2,%3};"
                 : "+f"(d0), "+f"(d1), "+f"(d2), "+f"(d3)
                 : "r"(a0), "r"(a1), "r"(a2), "r"(a3), "r"(b0), "r"(b1));
}
__device__ __forceinline__ void cp16(uint32_t dst, const void* src) {
    asm volatile("cp.async.ca.shared.global [%0],[%1],16;" :: "r"(dst), "l"(src));
}
__device__ __forceinline__ uint32_t pack2(__nv_bfloat16 a, __nv_bfloat16 b) {
    return (uint32_t)__bfloat16_as_ushort(a) | ((uint32_t)__bfloat16_as_ushort(b) << 16);
}

// One-shot per launch: split fp32 weights into bf16 hi/lo, packed per block slice.
// packed col n within slice ns: j = ns*12 + (n>>2), gate = n&3, G = gate*384 + j.
__global__ void pack_weights(const float* __restrict__ W_ih, const float* __restrict__ W_hh) {
    const long total = 4L * 32 * NCH * 48 * KC;   // 7,077,888
    for (long idx = (long)blockIdx.x * blockDim.x + threadIdx.x; idx < total;
         idx += (long)gridDim.x * blockDim.x) {
        int k  = (int)(idx % KC);
        long r = idx / KC;
        int n  = (int)(r % 48); r /= 48;
        int ch = (int)(r % NCH); r /= NCH;
        int ns = (int)(r % 32);
        int cell = (int)(r / 32);
        int j = ns * 12 + (n >> 2);
        int G = (n & 3) * 384 + j;
        int kg = ch * KC + k;
        float w = (kg < 768) ? W_ih[((long)cell * 1536 + G) * 768 + kg]
                             : W_hh[((long)cell * 1536 + G) * 384 + (kg - 768)];
        __nv_bfloat16 hi = __float2bfloat16(w);
        __nv_bfloat16 lo = __float2bfloat16(w - __bfloat162float(hi));
        g_wpk[cell][ns][ch][0][n][k] = hi;
        g_wpk[cell][ns][ch][1][n][k] = lo;
    }
}

__global__ __launch_bounds__(NTHR, 1)
void lstm_mma(const int*   __restrict__ contexts,   // [64][200]
              const int*   __restrict__ positions,  // [64]
              const float* __restrict__ W_emb,      // [50000][768]
              const float* __restrict__ b_lstm,     // [4][1536]
              const float* __restrict__ W_cls,      // [2][768]
              const float* __restrict__ b_cls,      // [2]
              float*       __restrict__ out)        // logits[128] | probs[128] | target[64*768]
{
    extern __shared__ __align__(16) char sm[];
    const uint32_t sb32 = (uint32_t)__cvta_generic_to_shared(sm);

    const int tid  = threadIdx.x;
    const int bid  = blockIdx.x;
    const int cell = bid >> 5;            // 0..3
    const int ns   = bid & 31;            // j-slice (12 j's)
    const bool isL1 = (cell >= 2);
    const int w    = tid >> 5;            // warp 0..15
    const int lane = tid & 31;
    const int kg   = w >> 3;              // k-group: 0 -> s 0..3, 1 -> s 4..7
    const int wl   = w & 7;
    const int mt   = wl & 3;              // m-tile (rows 16mt..16mt+15)
    const int ng   = wl >> 2;             // n-group (cols 24ng..24ng+23)

    // ---- per-lane ldmatrix offsets (byte offsets inside a term region) ----
    const uint32_t a_off = (uint32_t)((mt * 16 + (lane & 7) + ((lane >> 3) & 1) * 8) * AROW
                                      + (lane >> 4) * 16);
    const int bm = lane >> 3;
    const uint32_t b01_off = (uint32_t)((ng * 24 + (bm >> 1) * 8 + (lane & 7)) * AROW + (bm & 1) * 16);
    const int ln2 = lane & 15;
    const uint32_t b2_off  = (uint32_t)((ng * 24 + 16 + (ln2 & 7)) * AROW + (ln2 >> 3) * 16);

    // ---- zero h state (both parities) ----
    {
        float4 z = make_float4(0.f, 0.f, 0.f, 0.f);
        float4* hp = (float4*)g_h;
        const int n4 = 2 * 4 * 64 * 384 / 4;
        for (int i = bid * NTHR + tid; i < n4; i += NBLK * NTHR) hp[i] = z;
    }
    grid_barrier();

    // ---- persistent per-thread state (meaningful in k-group 0 warps) ----
    const int r0 = mt * 16 + (lane >> 2);             // my row, and r0+8
    const int q  = lane & 3;
    float cst[6] = {0, 0, 0, 0, 0, 0};                // [nt][row0/row1], even-q lanes of kg0
    const int pr0 = __ldg(&positions[r0]);
    const int pr1 = __ldg(&positions[r0 + 8]);
    float* tgt = out + 256;

    // biases for my 2 columns per n-tile: col = nb + 2q (+1)
    float bc0[3], bc1[3];
    #pragma unroll
    for (int nt = 0; nt < 3; nt++) {
        const int nb = ng * 24 + nt * 8;
        const int c0 = nb + 2 * q;
        const int G0 = (c0 & 3) * 384 + ns * 12 + (c0 >> 2);
        const int c1 = c0 + 1;
        const int G1 = (c1 & 3) * 384 + ns * 12 + (c1 >> 2);
        bc0[nt] = __ldg(&b_lstm[cell * 1536 + G0]);
        bc1[nt] = __ldg(&b_lstm[cell * 1536 + G1]);
    }

    const char* wsrc_base = (const char*)&g_wpk[cell][ns][0][0][0][0];

    for (int p = 0; p <= LDOC; p++) {
        const int par_w = p & 1;
        const int par_r = par_w ^ 1;
        const int t = isL1 ? (p - 1) : p;
        const bool active = isL1 ? (p >= 1) : (p < LDOC);

        if (active) {
            float acc[12];
            #pragma unroll
            for (int nt = 0; nt < 3; nt++) {
                // kg0 carries the bias; kg1 partials start at 0
                const float z0 = (kg == 0) ? bc0[nt] : 0.f;
                const float z1 = (kg == 0) ? bc1[nt] : 0.f;
                acc[nt * 4 + 0] = z0; acc[nt * 4 + 1] = z1;
                acc[nt * 4 + 2] = z0; acc[nt * 4 + 3] = z1;
            }

            // ---------- staging helpers ----------
            auto stage_W = [&](int ch, int b) {
                const char* src = wsrc_base + (long)ch * (2 * 48 * KC * 2);
                const uint32_t base = sb32 + b * BUF_SZ + 2 * A_SZ;
                for (int g16 = tid; g16 < 1536; g16 += NTHR) {
                    const int tm2 = g16 / 768;
                    const int rem = g16 - tm2 * 768;
                    const int n = rem >> 4, c = rem & 15;
                    cp16(base + tm2 * B_SZ + n * AROW + c * 16, src + (long)g16 * 16);
                }
                asm volatile("cp.async.commit_group;");
            };
            auto load_x = [&](int ch, float4* xa) {
                #pragma unroll
                for (int ii = 0; ii < 4; ii++) {
                    const int f = tid + ii * NTHR;
                    const int row = f >> 5, kc4 = f & 31;
                    const int kgl = ch * KC + kc4 * 4;
                    const float* src;
                    bool use_ldg = false;
                    if (!isL1) {
                        if (kgl < 768) {
                            const int tok = __ldg(&contexts[row * LDOC + t]);
                            src = W_emb + (size_t)tok * 768 + kgl;
                            use_ldg = true;
                        } else src = &g_h[par_r][cell][row][kgl - 768];
                    } else {
                        if (kgl < 384)      src = &g_h[par_r][0][row][kgl];
                        else if (kgl < 768) src = &g_h[par_r][1][row][kgl - 384];
                        else                src = &g_h[par_r][cell][row][kgl - 768];
                    }
                    xa[ii] = use_ldg ? __ldg((const float4*)src) : __ldcg((const float4*)src);
                }
            };
            auto store_x = [&](const float4* xa, int b) {
                char* ah = sm + b * BUF_SZ;
                char* al = ah + A_SZ;
                #pragma unroll
                for (int ii = 0; ii < 4; ii++) {
                    const int f = tid + ii * NTHR;
                    const int row = f >> 5, kc4 = f & 31;
                    const float4 x = xa[ii];
                    __nv_bfloat16 h0 = __float2bfloat16(x.x), h1 = __float2bfloat16(x.y);
                    __nv_bfloat16 h2 = __float2bfloat16(x.z), h3 = __float2bfloat16(x.w);
                    __nv_bfloat16 l0 = __float2bfloat16(x.x - __bfloat162float(h0));
                    __nv_bfloat16 l1 = __float2bfloat16(x.y - __bfloat162float(h1));
                    __nv_bfloat16 l2 = __float2bfloat16(x.z - __bfloat162float(h2));
                    __nv_bfloat16 l3 = __float2bfloat16(x.w - __bfloat162float(h3));
                    *(uint2*)(ah + row * AROW + kc4 * 8) = make_uint2(pack2(h0, h1), pack2(h2, h3));
                    *(uint2*)(al + row * AROW + kc4 * 8) = make_uint2(pack2(l0, l1), pack2(l2, l3));
                }
            };
            auto mma_chunk = [&](int b) {
                const uint32_t ah_b = sb32 + b * BUF_SZ;
                const uint32_t al_b = ah_b + A_SZ;
                const uint32_t bh_b = ah_b + 2 * A_SZ;
                const uint32_t bl_b = bh_b + B_SZ;
                #pragma unroll
                for (int s = 0; s < 4; s++) {
                    const uint32_t so = (uint32_t)(kg * 4 + s) * 32;
                    uint32_t ah[4], al[4], bh[6], bl[6];
                    ldsm_x4(ah[0], ah[1], ah[2], ah[3], ah_b + a_off + so);
                    ldsm_x4(al[0], al[1], al[2], al[3], al_b + a_off + so);
                    ldsm_x4(bh[0], bh[1], bh[2], bh[3], bh_b + b01_off + so);
                    ldsm_x2(bh[4], bh[5], bh_b + b2_off + so);
                    ldsm_x4(bl[0], bl[1], bl[2], bl[3], bl_b + b01_off + so);
                    ldsm_x2(bl[4], bl[5], bl_b + b2_off + so);
                    #pragma unroll
                    for (int nt = 0; nt < 3; nt++) {
                        float* c = acc + nt * 4;
                        mma_bf16(c[0], c[1], c[2], c[3], ah[0], ah[1], ah[2], ah[3], bh[nt * 2], bh[nt * 2 + 1]);
                        mma_bf16(c[0], c[1], c[2], c[3], ah[0], ah[1], ah[2], ah[3], bl[nt * 2], bl[nt * 2 + 1]);
                        mma_bf16(c[0], c[1], c[2], c[3], al[0], al[1], al[2], al[3], bh[nt * 2], bh[nt * 2 + 1]);
                    }
                }
            };
            // ---------- pipelined chunk loop ----------
            {
                float4 xa[4];
                stage_W(0, 0);
                load_x(0, xa);
                store_x(xa, 0);
                asm volatile("cp.async.wait_group 0;");
                __syncthreads();
                for (int i = 0; i < NCH; i++) {
                    const int b = i & 1;
                    if (i + 1 < NCH) { stage_W(i + 1, b ^ 1); load_x(i + 1, xa); }
                    mma_chunk(b);
                    if (i + 1 < NCH) {
                        store_x(xa, b ^ 1);
                        asm volatile("cp.async.wait_group 0;");
                    }
                    __syncthreads();
                }
            }

            // ---------- k-reduction: kg1 partials -> kg0 via smem (pad-13 stride) ----------
            {
                float* red = (float*)sm;
                if (kg == 1) {
                    float* dst = red + (wl * 32 + lane) * 13;
                    #pragma unroll
                    for (int i = 0; i < 12; i++) dst[i] = acc[i];
                }
                __syncthreads();
                if (kg == 0) {
                    const float* src = red + (wl * 32 + lane) * 13;
                    #pragma unroll
                    for (int i = 0; i < 12; i++) acc[i] += src[i];
                }
            }

            // ---------- epilogue (kg0 warps): assemble i,f,g,o via shfl, update c, store h ----------
            if (kg == 0) {
                #pragma unroll
                for (int nt = 0; nt < 3; nt++) {
                    float* a = acc + nt * 4;
                    const float p0 = __shfl_xor_sync(0xFFFFFFFFu, a[0], 1);
                    const float p1 = __shfl_xor_sync(0xFFFFFFFFu, a[1], 1);
                    const float p2 = __shfl_xor_sync(0xFFFFFFFFu, a[2], 1);
                    const float p3 = __shfl_xor_sync(0xFFFFFFFFu, a[3], 1);
                    if ((lane & 1) == 0) {
                        const int jg = ns * 12 + (ng * 6 + nt * 2) + (q >> 1);
                        float cn0 = sigm(a[1]) * cst[nt * 2 + 0] + sigm(a[0]) * tanhf(p0);
                        float h0v = sigm(p1) * tanhf(cn0);
                        float cn1 = sigm(a[3]) * cst[nt * 2 + 1] + sigm(a[2]) * tanhf(p2);
                        float h1v = sigm(p3) * tanhf(cn1);
                        cst[nt * 2 + 0] = cn0;
                        cst[nt * 2 + 1] = cn1;
                        __stcg(&g_h[par_w][cell][r0][jg], h0v);
                        __stcg(&g_h[par_w][cell][r0 + 8][jg], h1v);
                        if (isL1) {
                            if (t == pr0) __stcg(&tgt[r0 * 768 + (cell - 2) * 384 + jg], h0v);
                            if (t == pr1) __stcg(&tgt[(r0 + 8) * 768 + (cell - 2) * 384 + jg], h1v);
                        }
                    }
                }
            }
        }
        grid_barrier();
    }

    // ---- classifier head ----
    if (bid == 0 && tid < 128) {
        const int b = tid >> 1;
        const int c = tid & 1;
        const float4* tv = (const float4*)(tgt + b * 768);
        const float4* wv = (const float4*)(W_cls + c * 768);
        float acc = __ldg(&b_cls[c]);
        #pragma unroll 4
        for (int qq = 0; qq < 192; qq++) {
            const float4 x = __ldcg(tv + qq);
            const float4 ww = __ldg(wv + qq);
            acc = fmaf(x.x, ww.x, acc);
            acc = fmaf(x.y, ww.y, acc);
            acc = fmaf(x.z, ww.z, acc);
            acc = fmaf(x.w, ww.w, acc);
        }
        out[tid] = acc;                              // logits [64][2]
        out[128 + tid] = 1.0f / (1.0f + expf(-acc)); // probs  [64][2]
    }
}

extern "C" void kernel_launch(void* const* d_in, const int* in_sizes, int n_in,
                              void* d_out, int out_size) {
    (void)in_sizes; (void)n_in; (void)out_size;
    cudaFuncSetAttribute(lstm_mma, cudaFuncAttributeMaxDynamicSharedMemorySize, SMEM_BYTES);
    pack_weights<<<512, 256>>>((const float*)d_in[3], (const float*)d_in[4]);
    lstm_mma<<<NBLK, NTHR, SMEM_BYTES>>>(
        (const int*)d_in[0],     // contexts
        (const int*)d_in[1],     // positions
        (const float*)d_in[2],   // W_emb
        (const float*)d_in[5],   // b_lstm
        (const float*)d_in[6],   // W_cls
        (const float*)d_in[7],   // b_cls
        (float*)d_out);
}